// round 1
// baseline (speedup 1.0000x reference)
#include <cuda_runtime.h>

#define S_   1024
#define H_   1024
#define B_   4
#define NH_  16
#define D_   64
#define BS_  4096
#define BH_  64

// ---------------- scratch (no allocs allowed) ----------------
__device__ float g_q[BS_ * H_];
__device__ float g_k[BS_ * H_];
__device__ float g_v[BS_ * H_];
__device__ float g_sc[(size_t)BH_ * S_ * S_];   // 256 MB scores/probs
__device__ float g_ctx[BS_ * H_];
__device__ float g_y[BS_ * H_];

// ---------------- GEMM NT: C[i,j] = sum_k A[i,k]*B[j,k] (+bias[j]) (+resid[i,j]) ----
template <bool BIAS, bool RESID>
__global__ void __launch_bounds__(256) gemm_nt(const float* __restrict__ A,
                                               const float* __restrict__ Bm,
                                               const float* __restrict__ bias,
                                               const float* __restrict__ resid,
                                               float* __restrict__ C,
                                               int M, int N, int K)
{
    __shared__ float sA[8][128];
    __shared__ float sB[8][128];
    const int tid = threadIdx.x;
    const int m0 = blockIdx.y * 128;
    const int n0 = blockIdx.x * 128;
    const int ty = tid >> 4, tx = tid & 15;
    const int ri = ty * 8, cj = tx * 8;
    const int lr = tid >> 1;
    const int lk = (tid & 1) * 4;

    float acc[8][8];
#pragma unroll
    for (int i = 0; i < 8; i++)
#pragma unroll
        for (int j = 0; j < 8; j++) acc[i][j] = 0.f;

    const float* Ap = A + (size_t)(m0 + lr) * K + lk;
    const float* Bp = Bm + (size_t)(n0 + lr) * K + lk;

    for (int k0 = 0; k0 < K; k0 += 8) {
        float4 a4 = *(const float4*)(Ap + k0);
        float4 b4 = *(const float4*)(Bp + k0);
        __syncthreads();
        sA[lk + 0][lr] = a4.x; sA[lk + 1][lr] = a4.y;
        sA[lk + 2][lr] = a4.z; sA[lk + 3][lr] = a4.w;
        sB[lk + 0][lr] = b4.x; sB[lk + 1][lr] = b4.y;
        sB[lk + 2][lr] = b4.z; sB[lk + 3][lr] = b4.w;
        __syncthreads();
#pragma unroll
        for (int kk = 0; kk < 8; kk++) {
            float av[8], bv[8];
            *(float4*)(av)     = *(const float4*)&sA[kk][ri];
            *(float4*)(av + 4) = *(const float4*)&sA[kk][ri + 4];
            *(float4*)(bv)     = *(const float4*)&sB[kk][cj];
            *(float4*)(bv + 4) = *(const float4*)&sB[kk][cj + 4];
#pragma unroll
            for (int i = 0; i < 8; i++)
#pragma unroll
                for (int j = 0; j < 8; j++)
                    acc[i][j] = fmaf(av[i], bv[j], acc[i][j]);
        }
    }

#pragma unroll
    for (int i = 0; i < 8; i++) {
        const int gi = m0 + ri + i;
#pragma unroll
        for (int j = 0; j < 8; j++) {
            const int gj = n0 + cj + j;
            float vv = acc[i][j];
            if (BIAS)  vv += bias[gj];
            if (RESID) vv += resid[(size_t)gi * N + gj];
            C[(size_t)gi * N + gj] = vv;
        }
    }
}

// ---------------- scores: qk^T + (q+k)·dist_emb[l-r+1023], scaled + mask ----------
// one block = 64(l) x 64(r) tile of one (b,h)
__global__ void __launch_bounds__(256) scores_kernel(
    const float* __restrict__ q, const float* __restrict__ k,
    const float* __restrict__ dist, const float* __restrict__ mask,
    float* __restrict__ sc)
{
    extern __shared__ float sm[];
    float* sQ = sm;                 // [64][65]
    float* sK = sm + 64 * 65;       // [64][65]
    float* sP = sm + 128 * 65;      // [127][65]

    const int l0 = blockIdx.x * 64;
    const int r0 = blockIdx.y * 64;
    const int bh = blockIdx.z;
    const int b = bh >> 4, h = bh & 15;
    const int tid = threadIdx.x;

    for (int idx = tid; idx < 64 * 16; idx += 256) {
        const int row = idx >> 4, c = (idx & 15) * 4;
        float4 qa = *(const float4*)(q + (size_t)(b * S_ + l0 + row) * H_ + h * D_ + c);
        float4 ka = *(const float4*)(k + (size_t)(b * S_ + r0 + row) * H_ + h * D_ + c);
        sQ[row * 65 + c + 0] = qa.x; sQ[row * 65 + c + 1] = qa.y;
        sQ[row * 65 + c + 2] = qa.z; sQ[row * 65 + c + 3] = qa.w;
        sK[row * 65 + c + 0] = ka.x; sK[row * 65 + c + 1] = ka.y;
        sK[row * 65 + c + 2] = ka.z; sK[row * 65 + c + 3] = ka.w;
    }
    // dist row for local t=0 is (l0 - r0 + 960); t in [0,126] always in [0,2046]
    const int prow0 = l0 - r0 + 960;
    for (int idx = tid; idx < 127 * 16; idx += 256) {
        const int t = idx >> 4, c = (idx & 15) * 4;
        float4 pa = *(const float4*)(dist + (size_t)(prow0 + t) * D_ + c);
        sP[t * 65 + c + 0] = pa.x; sP[t * 65 + c + 1] = pa.y;
        sP[t * 65 + c + 2] = pa.z; sP[t * 65 + c + 3] = pa.w;
    }
    __syncthreads();

    const int ty = tid >> 4, tx = tid & 15;
    const int tb = ty - tx + 63;
    float acc[4][4] = {};

#pragma unroll 2
    for (int d = 0; d < 64; d++) {
        float qv[4], kv[4], pv[7];
#pragma unroll
        for (int m = 0; m < 4; m++) qv[m] = sQ[(ty + 16 * m) * 65 + d];
#pragma unroll
        for (int n = 0; n < 4; n++) kv[n] = sK[(tx + 16 * n) * 65 + d];
#pragma unroll
        for (int u = 0; u < 7; u++) pv[u] = sP[(tb + 16 * (u - 3)) * 65 + d];
#pragma unroll
        for (int m = 0; m < 4; m++)
#pragma unroll
            for (int n = 0; n < 4; n++) {
                acc[m][n] = fmaf(qv[m], kv[n], acc[m][n]);
                acc[m][n] = fmaf(qv[m] + kv[n], pv[m - n + 3], acc[m][n]);
            }
    }

#pragma unroll
    for (int m = 0; m < 4; m++) {
        const int l = l0 + ty + 16 * m;
#pragma unroll
        for (int n = 0; n < 4; n++) {
            const int r = r0 + tx + 16 * n;
            sc[((size_t)bh * S_ + l) * S_ + r] = acc[m][n] * 0.125f + mask[b * S_ + r];
        }
    }
}

// ---------------- softmax over last dim (rows of 1024) -----------------------------
__global__ void __launch_bounds__(256) softmax_kernel(float* __restrict__ sc)
{
    __shared__ float sred[8];
    __shared__ float sbc;
    const size_t row = blockIdx.x;
    float* p = sc + row * S_;
    const int tid = threadIdx.x;
    const int lane = tid & 31, wid = tid >> 5;

    float4 v = ((const float4*)p)[tid];

    float m = fmaxf(fmaxf(v.x, v.y), fmaxf(v.z, v.w));
#pragma unroll
    for (int o = 16; o > 0; o >>= 1) m = fmaxf(m, __shfl_xor_sync(~0u, m, o));
    if (lane == 0) sred[wid] = m;
    __syncthreads();
    if (tid == 0) {
        float t = sred[0];
#pragma unroll
        for (int i = 1; i < 8; i++) t = fmaxf(t, sred[i]);
        sbc = t;
    }
    __syncthreads();
    const float bm = sbc;

    float e0 = __expf(v.x - bm), e1 = __expf(v.y - bm);
    float e2 = __expf(v.z - bm), e3 = __expf(v.w - bm);
    float s = e0 + e1 + e2 + e3;
#pragma unroll
    for (int o = 16; o > 0; o >>= 1) s += __shfl_xor_sync(~0u, s, o);
    if (lane == 0) sred[wid] = s;
    __syncthreads();
    if (tid == 0) {
        float t = 0.f;
#pragma unroll
        for (int i = 0; i < 8; i++) t += sred[i];
        sbc = t;
    }
    __syncthreads();
    const float inv = 1.f / sbc;

    v.x = e0 * inv; v.y = e1 * inv; v.z = e2 * inv; v.w = e3 * inv;
    ((float4*)p)[tid] = v;
}

// ---------------- ctx = probs @ V  (per (b,h), 64(l) x 64(d) tiles) ---------------
__global__ void __launch_bounds__(256) ctx_kernel(const float* __restrict__ probs,
                                                  const float* __restrict__ v,
                                                  float* __restrict__ ctx)
{
    __shared__ float sPb[64 * 65];
    __shared__ float sV[64 * 65];
    const int l0 = blockIdx.x * 64;
    const int bh = blockIdx.y;
    const int b = bh >> 4, h = bh & 15;
    const int tid = threadIdx.x;
    const int ty = tid >> 4, tx = tid & 15;

    float acc[4][4] = {};

    for (int r0 = 0; r0 < S_; r0 += 64) {
        __syncthreads();
        for (int idx = tid; idx < 64 * 16; idx += 256) {
            const int row = idx >> 4, c = (idx & 15) * 4;
            float4 pa = *(const float4*)(probs + ((size_t)bh * S_ + l0 + row) * S_ + r0 + c);
            float4 va = *(const float4*)(v + (size_t)(b * S_ + r0 + row) * H_ + h * D_ + c);
            sPb[row * 65 + c + 0] = pa.x; sPb[row * 65 + c + 1] = pa.y;
            sPb[row * 65 + c + 2] = pa.z; sPb[row * 65 + c + 3] = pa.w;
            sV[row * 65 + c + 0] = va.x; sV[row * 65 + c + 1] = va.y;
            sV[row * 65 + c + 2] = va.z; sV[row * 65 + c + 3] = va.w;
        }
        __syncthreads();
#pragma unroll 4
        for (int rr = 0; rr < 64; rr++) {
            float pvv[4], vv[4];
#pragma unroll
            for (int m = 0; m < 4; m++) pvv[m] = sPb[(ty + 16 * m) * 65 + rr];
#pragma unroll
            for (int n = 0; n < 4; n++) vv[n] = sV[rr * 65 + tx + 16 * n];
#pragma unroll
            for (int m = 0; m < 4; m++)
#pragma unroll
                for (int n = 0; n < 4; n++)
                    acc[m][n] = fmaf(pvv[m], vv[n], acc[m][n]);
        }
    }

#pragma unroll
    for (int m = 0; m < 4; m++) {
        const int l = l0 + ty + 16 * m;
#pragma unroll
        for (int n = 0; n < 4; n++)
            ctx[(size_t)(b * S_ + l) * H_ + h * D_ + tx + 16 * n] = acc[m][n];
    }
}

// ---------------- LayerNorm over H per token ---------------------------------------
__global__ void __launch_bounds__(256) ln_kernel(const float* __restrict__ y,
                                                 const float* __restrict__ g,
                                                 const float* __restrict__ bb,
                                                 float* __restrict__ out)
{
    __shared__ float sred[8];
    __shared__ float sbc;
    const size_t row = blockIdx.x;
    const int tid = threadIdx.x;
    const int lane = tid & 31, wid = tid >> 5;

    float4 v = ((const float4*)(y + row * H_))[tid];

    float s = v.x + v.y + v.z + v.w;
#pragma unroll
    for (int o = 16; o > 0; o >>= 1) s += __shfl_xor_sync(~0u, s, o);
    if (lane == 0) sred[wid] = s;
    __syncthreads();
    if (tid == 0) {
        float t = 0.f;
#pragma unroll
        for (int i = 0; i < 8; i++) t += sred[i];
        sbc = t;
    }
    __syncthreads();
    const float mu = sbc * (1.f / H_);

    float dx = v.x - mu, dy = v.y - mu, dz = v.z - mu, dw = v.w - mu;
    float q = dx * dx + dy * dy + dz * dz + dw * dw;
#pragma unroll
    for (int o = 16; o > 0; o >>= 1) q += __shfl_xor_sync(~0u, q, o);
    if (lane == 0) sred[wid] = q;
    __syncthreads();
    if (tid == 0) {
        float t = 0.f;
#pragma unroll
        for (int i = 0; i < 8; i++) t += sred[i];
        sbc = t;
    }
    __syncthreads();
    const float rstd = rsqrtf(sbc * (1.f / H_) + 1e-12f);

    float4 gg = ((const float4*)g)[tid];
    float4 bt = ((const float4*)bb)[tid];
    float4 o;
    o.x = dx * rstd * gg.x + bt.x;
    o.y = dy * rstd * gg.y + bt.y;
    o.z = dz * rstd * gg.z + bt.z;
    o.w = dw * rstd * gg.w + bt.w;
    ((float4*)(out + row * H_))[tid] = o;
}

// ---------------- launch -----------------------------------------------------------
extern "C" void kernel_launch(void* const* d_in, const int* in_sizes, int n_in,
                              void* d_out, int out_size)
{
    (void)in_sizes; (void)n_in; (void)out_size;
    const float* x    = (const float*)d_in[0];
    const float* mask = (const float*)d_in[1];
    const float* Wq   = (const float*)d_in[2];
    const float* bq   = (const float*)d_in[3];
    const float* Wk   = (const float*)d_in[4];
    const float* bk   = (const float*)d_in[5];
    const float* Wv   = (const float*)d_in[6];
    const float* bv   = (const float*)d_in[7];
    const float* de   = (const float*)d_in[8];
    const float* Wo   = (const float*)d_in[9];
    const float* bo   = (const float*)d_in[10];
    const float* lng  = (const float*)d_in[11];
    const float* lnb  = (const float*)d_in[12];
    float* out = (float*)d_out;

    float *q, *k, *v, *sc, *ctx, *y;
    cudaGetSymbolAddress((void**)&q,   g_q);
    cudaGetSymbolAddress((void**)&k,   g_k);
    cudaGetSymbolAddress((void**)&v,   g_v);
    cudaGetSymbolAddress((void**)&sc,  g_sc);
    cudaGetSymbolAddress((void**)&ctx, g_ctx);
    cudaGetSymbolAddress((void**)&y,   g_y);

    const dim3 gg(H_ / 128, BS_ / 128);
    gemm_nt<true, false><<<gg, 256>>>(x, Wq, bq, nullptr, q, BS_, H_, H_);
    gemm_nt<true, false><<<gg, 256>>>(x, Wk, bk, nullptr, k, BS_, H_, H_);
    gemm_nt<true, false><<<gg, 256>>>(x, Wv, bv, nullptr, v, BS_, H_, H_);

    const int SC_SMEM = (64 + 64 + 127) * 65 * 4;  // 66300 B
    cudaFuncSetAttribute(scores_kernel, cudaFuncAttributeMaxDynamicSharedMemorySize, SC_SMEM);
    scores_kernel<<<dim3(16, 16, 64), 256, SC_SMEM>>>(q, k, de, mask, sc);

    softmax_kernel<<<BH_ * S_, 256>>>(sc);

    ctx_kernel<<<dim3(16, 64), 256>>>(sc, v, ctx);

    gemm_nt<true, true><<<gg, 256>>>(ctx, Wo, bo, x, y, BS_, H_, H_);

    ln_kernel<<<BS_, 256>>>(y, lng, lnb, out);
}